// round 10
// baseline (speedup 1.0000x reference)
#include <cuda_runtime.h>
#include <cuda_bf16.h>

// NeuralODE: y_{t+1} = y_t + dt * MLP(y_t), 199 steps, B=4096, D=64, H=256.
// Rows are independent -> single persistent-style kernel, each CTA owns 32 rows
// for all 200 steps. W1/W3/biases cached in SMEM; W2 (256KB) streamed from L2
// once per CTA per step with register accumulators acc[32] per thread.

#define ROWS 32
#define TH   256

static constexpr int Bsz = 4096;
static constexpr int Dd  = 64;
static constexpr int Hh  = 256;
static constexpr int Tt  = 200;

// SMEM layout (floats)
static constexpr int OFF_W1 = 0;                 // 64*256   = 16384
static constexpr int OFF_W3 = OFF_W1 + 64*256;   // 256*64   = 16384
static constexpr int OFF_H1 = OFF_W3 + 256*64;   // ROWS*256 = 8192
static constexpr int OFF_H2 = OFF_H1 + ROWS*256; // ROWS*256 = 8192
static constexpr int OFF_Y  = OFF_H2 + ROWS*256; // ROWS*64  = 2048
static constexpr int OFF_B1 = OFF_Y  + ROWS*64;  // 256
static constexpr int OFF_B2 = OFF_B1 + 256;      // 256
static constexpr int OFF_B3 = OFF_B2 + 256;      // 64
static constexpr int SMEM_FLOATS = OFF_B3 + 64;
static constexpr size_t SMEM_BYTES = (size_t)SMEM_FLOATS * sizeof(float);

__global__ __launch_bounds__(TH, 1)
void node_kernel(const float* __restrict__ y0, const float* __restrict__ tvec,
                 const float* __restrict__ W1, const float* __restrict__ b1,
                 const float* __restrict__ W2, const float* __restrict__ b2,
                 const float* __restrict__ W3, const float* __restrict__ b3,
                 float* __restrict__ out)
{
    extern __shared__ float smem[];
    float* sW1 = smem + OFF_W1;
    float* sW3 = smem + OFF_W3;
    float* sh1 = smem + OFF_H1;
    float* sh2 = smem + OFF_H2;
    float* sy  = smem + OFF_Y;
    float* sb1 = smem + OFF_B1;
    float* sb2 = smem + OFF_B2;
    float* sb3 = smem + OFF_B3;

    const int tid  = threadIdx.x;
    const int row0 = blockIdx.x * ROWS;

    // ---- Prologue: stage weights + y0, write t=0 output ----
    for (int i = tid; i < 64*256; i += TH) sW1[i] = W1[i];
    for (int i = tid; i < 256*64; i += TH) sW3[i] = W3[i];
    if (tid < 256) { sb1[tid] = b1[tid]; sb2[tid] = b2[tid]; }
    if (tid < 64)  { sb3[tid] = b3[tid]; }
    for (int i = tid; i < ROWS*64; i += TH) {
        float v = y0[(size_t)row0*64 + i];
        sy[i] = v;
        int r = i >> 6, d = i & 63;
        out[(size_t)(row0 + r) * Tt * 64 + d] = v;   // t = 0
    }
    const float dt = tvec[1] - tvec[0];
    __syncthreads();

    for (int step = 1; step < Tt; ++step) {
        // ---- GEMM1: h1 = relu(y @ W1 + b1)   [ROWS x 256] ----
        {
            const int j = tid;
            float acc[ROWS];
            #pragma unroll
            for (int r = 0; r < ROWS; r++) acc[r] = 0.f;

            #pragma unroll 1
            for (int k = 0; k < 64; k += 4) {
                const float w0 = sW1[(k+0)*256 + j];
                const float w1 = sW1[(k+1)*256 + j];
                const float w2 = sW1[(k+2)*256 + j];
                const float w3 = sW1[(k+3)*256 + j];
                #pragma unroll
                for (int r = 0; r < ROWS; r++) {
                    float4 yv = *(const float4*)&sy[r*64 + k];   // broadcast
                    acc[r] += yv.x*w0 + yv.y*w1 + yv.z*w2 + yv.w*w3;
                }
            }
            const float bb = sb1[j];
            #pragma unroll
            for (int r = 0; r < ROWS; r++)
                sh1[r*256 + j] = fmaxf(acc[r] + bb, 0.f);
        }
        __syncthreads();

        // ---- GEMM2: h2 = relu(h1 @ W2 + b2)   [ROWS x 256], W2 from L2 ----
        {
            const int j = tid;
            float acc[ROWS];
            #pragma unroll
            for (int r = 0; r < ROWS; r++) acc[r] = 0.f;

            // software-pipelined W2 column loads (prefetch next k-quad)
            float w[4], wn[4];
            #pragma unroll
            for (int i = 0; i < 4; i++) w[i] = W2[i*256 + j];

            #pragma unroll 1
            for (int k = 0; k < 256; k += 4) {
                const int kn = (k + 4) & 255;   // wrap keeps loads in-bounds
                #pragma unroll
                for (int i = 0; i < 4; i++) wn[i] = W2[(kn + i)*256 + j];

                #pragma unroll
                for (int r = 0; r < ROWS; r++) {
                    float4 hv = *(const float4*)&sh1[r*256 + k];  // broadcast
                    acc[r] += hv.x*w[0] + hv.y*w[1] + hv.z*w[2] + hv.w*w[3];
                }
                #pragma unroll
                for (int i = 0; i < 4; i++) w[i] = wn[i];
            }
            const float bb = sb2[j];
            #pragma unroll
            for (int r = 0; r < ROWS; r++)
                sh2[r*256 + j] = fmaxf(acc[r] + bb, 0.f);
        }
        __syncthreads();

        // ---- GEMM3 + Euler update: y += dt*(h2 @ W3 + b3), stream to out ----
        {
            const int d  = tid & 63;
            const int rg = tid >> 6;         // 0..3, 8 rows each
            float acc[8];
            #pragma unroll
            for (int r = 0; r < 8; r++) acc[r] = 0.f;

            #pragma unroll 1
            for (int k = 0; k < 256; k += 4) {
                const float w0 = sW3[(k+0)*64 + d];
                const float w1 = sW3[(k+1)*64 + d];
                const float w2 = sW3[(k+2)*64 + d];
                const float w3 = sW3[(k+3)*64 + d];
                #pragma unroll
                for (int r = 0; r < 8; r++) {
                    float4 hv = *(const float4*)&sh2[(rg*8 + r)*256 + k];
                    acc[r] += hv.x*w0 + hv.y*w1 + hv.z*w2 + hv.w*w3;
                }
            }
            const float bb = sb3[d];
            #pragma unroll
            for (int r = 0; r < 8; r++) {
                const int rr = rg*8 + r;
                float ynew = sy[rr*64 + d] + dt * (acc[r] + bb);
                sy[rr*64 + d] = ynew;
                out[(size_t)(row0 + rr) * Tt * 64 + (size_t)step * 64 + d] = ynew;
            }
        }
        __syncthreads();
    }
}

extern "C" void kernel_launch(void* const* d_in, const int* in_sizes, int n_in,
                              void* d_out, int out_size)
{
    const float* y0 = (const float*)d_in[0];
    const float* t  = (const float*)d_in[1];
    const float* W1 = (const float*)d_in[2];
    const float* b1 = (const float*)d_in[3];
    const float* W2 = (const float*)d_in[4];
    const float* b2 = (const float*)d_in[5];
    const float* W3 = (const float*)d_in[6];
    const float* b3 = (const float*)d_in[7];
    float* out = (float*)d_out;

    static bool attr_set = false;
    if (!attr_set) {
        cudaFuncSetAttribute(node_kernel,
                             cudaFuncAttributeMaxDynamicSharedMemorySize,
                             (int)SMEM_BYTES);
        attr_set = true;
    }

    node_kernel<<<Bsz / ROWS, TH, SMEM_BYTES>>>(y0, t, W1, b1, W2, b2, W3, b3, out);
}

// round 11
// speedup vs baseline: 1.0011x; 1.0011x over previous
#include <cuda_runtime.h>
#include <cuda_bf16.h>

// NeuralODE: y_{t+1} = y_t + dt * MLP(y_t), 199 steps, B=4096, D=64, H=256.
// Rows are independent -> single persistent-style kernel, each CTA owns 32 rows
// for all 200 steps. W1/W3/biases cached in SMEM; W2 (256KB) streamed from L2
// once per CTA per step with register accumulators acc[32] per thread.

#define ROWS 32
#define TH   256

static constexpr int Bsz = 4096;
static constexpr int Dd  = 64;
static constexpr int Hh  = 256;
static constexpr int Tt  = 200;

// SMEM layout (floats)
static constexpr int OFF_W1 = 0;                 // 64*256   = 16384
static constexpr int OFF_W3 = OFF_W1 + 64*256;   // 256*64   = 16384
static constexpr int OFF_H1 = OFF_W3 + 256*64;   // ROWS*256 = 8192
static constexpr int OFF_H2 = OFF_H1 + ROWS*256; // ROWS*256 = 8192
static constexpr int OFF_Y  = OFF_H2 + ROWS*256; // ROWS*64  = 2048
static constexpr int OFF_B1 = OFF_Y  + ROWS*64;  // 256
static constexpr int OFF_B2 = OFF_B1 + 256;      // 256
static constexpr int OFF_B3 = OFF_B2 + 256;      // 64
static constexpr int SMEM_FLOATS = OFF_B3 + 64;
static constexpr size_t SMEM_BYTES = (size_t)SMEM_FLOATS * sizeof(float);

__global__ __launch_bounds__(TH, 1)
void node_kernel(const float* __restrict__ y0, const float* __restrict__ tvec,
                 const float* __restrict__ W1, const float* __restrict__ b1,
                 const float* __restrict__ W2, const float* __restrict__ b2,
                 const float* __restrict__ W3, const float* __restrict__ b3,
                 float* __restrict__ out)
{
    extern __shared__ float smem[];
    float* sW1 = smem + OFF_W1;
    float* sW3 = smem + OFF_W3;
    float* sh1 = smem + OFF_H1;
    float* sh2 = smem + OFF_H2;
    float* sy  = smem + OFF_Y;
    float* sb1 = smem + OFF_B1;
    float* sb2 = smem + OFF_B2;
    float* sb3 = smem + OFF_B3;

    const int tid  = threadIdx.x;
    const int row0 = blockIdx.x * ROWS;

    // ---- Prologue: stage weights + y0, write t=0 output ----
    for (int i = tid; i < 64*256; i += TH) sW1[i] = W1[i];
    for (int i = tid; i < 256*64; i += TH) sW3[i] = W3[i];
    if (tid < 256) { sb1[tid] = b1[tid]; sb2[tid] = b2[tid]; }
    if (tid < 64)  { sb3[tid] = b3[tid]; }
    for (int i = tid; i < ROWS*64; i += TH) {
        float v = y0[(size_t)row0*64 + i];
        sy[i] = v;
        int r = i >> 6, d = i & 63;
        out[(size_t)(row0 + r) * Tt * 64 + d] = v;   // t = 0
    }
    const float dt = tvec[1] - tvec[0];
    __syncthreads();

    for (int step = 1; step < Tt; ++step) {
        // ---- GEMM1: h1 = relu(y @ W1 + b1)   [ROWS x 256] ----
        {
            const int j = tid;
            float acc[ROWS];
            #pragma unroll
            for (int r = 0; r < ROWS; r++) acc[r] = 0.f;

            #pragma unroll 1
            for (int k = 0; k < 64; k += 4) {
                const float w0 = sW1[(k+0)*256 + j];
                const float w1 = sW1[(k+1)*256 + j];
                const float w2 = sW1[(k+2)*256 + j];
                const float w3 = sW1[(k+3)*256 + j];
                #pragma unroll
                for (int r = 0; r < ROWS; r++) {
                    float4 yv = *(const float4*)&sy[r*64 + k];   // broadcast
                    acc[r] += yv.x*w0 + yv.y*w1 + yv.z*w2 + yv.w*w3;
                }
            }
            const float bb = sb1[j];
            #pragma unroll
            for (int r = 0; r < ROWS; r++)
                sh1[r*256 + j] = fmaxf(acc[r] + bb, 0.f);
        }
        __syncthreads();

        // ---- GEMM2: h2 = relu(h1 @ W2 + b2)   [ROWS x 256], W2 from L2 ----
        {
            const int j = tid;
            float acc[ROWS];
            #pragma unroll
            for (int r = 0; r < ROWS; r++) acc[r] = 0.f;

            // software-pipelined W2 column loads (prefetch next k-quad)
            float w[4], wn[4];
            #pragma unroll
            for (int i = 0; i < 4; i++) w[i] = W2[i*256 + j];

            #pragma unroll 1
            for (int k = 0; k < 256; k += 4) {
                const int kn = (k + 4) & 255;   // wrap keeps loads in-bounds
                #pragma unroll
                for (int i = 0; i < 4; i++) wn[i] = W2[(kn + i)*256 + j];

                #pragma unroll
                for (int r = 0; r < ROWS; r++) {
                    float4 hv = *(const float4*)&sh1[r*256 + k];  // broadcast
                    acc[r] += hv.x*w[0] + hv.y*w[1] + hv.z*w[2] + hv.w*w[3];
                }
                #pragma unroll
                for (int i = 0; i < 4; i++) w[i] = wn[i];
            }
            const float bb = sb2[j];
            #pragma unroll
            for (int r = 0; r < ROWS; r++)
                sh2[r*256 + j] = fmaxf(acc[r] + bb, 0.f);
        }
        __syncthreads();

        // ---- GEMM3 + Euler update: y += dt*(h2 @ W3 + b3), stream to out ----
        {
            const int d  = tid & 63;
            const int rg = tid >> 6;         // 0..3, 8 rows each
            float acc[8];
            #pragma unroll
            for (int r = 0; r < 8; r++) acc[r] = 0.f;

            #pragma unroll 1
            for (int k = 0; k < 256; k += 4) {
                const float w0 = sW3[(k+0)*64 + d];
                const float w1 = sW3[(k+1)*64 + d];
                const float w2 = sW3[(k+2)*64 + d];
                const float w3 = sW3[(k+3)*64 + d];
                #pragma unroll
                for (int r = 0; r < 8; r++) {
                    float4 hv = *(const float4*)&sh2[(rg*8 + r)*256 + k];
                    acc[r] += hv.x*w0 + hv.y*w1 + hv.z*w2 + hv.w*w3;
                }
            }
            const float bb = sb3[d];
            #pragma unroll
            for (int r = 0; r < 8; r++) {
                const int rr = rg*8 + r;
                float ynew = sy[rr*64 + d] + dt * (acc[r] + bb);
                sy[rr*64 + d] = ynew;
                out[(size_t)(row0 + rr) * Tt * 64 + (size_t)step * 64 + d] = ynew;
            }
        }
        __syncthreads();
    }
}

extern "C" void kernel_launch(void* const* d_in, const int* in_sizes, int n_in,
                              void* d_out, int out_size)
{
    const float* y0 = (const float*)d_in[0];
    const float* t  = (const float*)d_in[1];
    const float* W1 = (const float*)d_in[2];
    const float* b1 = (const float*)d_in[3];
    const float* W2 = (const float*)d_in[4];
    const float* b2 = (const float*)d_in[5];
    const float* W3 = (const float*)d_in[6];
    const float* b3 = (const float*)d_in[7];
    float* out = (float*)d_out;

    static bool attr_set = false;
    if (!attr_set) {
        cudaFuncSetAttribute(node_kernel,
                             cudaFuncAttributeMaxDynamicSharedMemorySize,
                             (int)SMEM_BYTES);
        attr_set = true;
    }

    node_kernel<<<Bsz / ROWS, TH, SMEM_BYTES>>>(y0, t, W1, b1, W2, b2, W3, b3, out);
}

// round 12
// speedup vs baseline: 1.0017x; 1.0006x over previous
#include <cuda_runtime.h>
#include <cuda_bf16.h>

// NeuralODE: y_{t+1} = y_t + dt * MLP(y_t), 199 steps, B=4096, D=64, H=256.
// Rows are independent -> single persistent-style kernel, each CTA owns 32 rows
// for all 200 steps. W1/W3/biases cached in SMEM; W2 (256KB) streamed from L2
// once per CTA per step with register accumulators acc[32] per thread.

#define ROWS 32
#define TH   256

static constexpr int Bsz = 4096;
static constexpr int Dd  = 64;
static constexpr int Hh  = 256;
static constexpr int Tt  = 200;

// SMEM layout (floats)
static constexpr int OFF_W1 = 0;                 // 64*256   = 16384
static constexpr int OFF_W3 = OFF_W1 + 64*256;   // 256*64   = 16384
static constexpr int OFF_H1 = OFF_W3 + 256*64;   // ROWS*256 = 8192
static constexpr int OFF_H2 = OFF_H1 + ROWS*256; // ROWS*256 = 8192
static constexpr int OFF_Y  = OFF_H2 + ROWS*256; // ROWS*64  = 2048
static constexpr int OFF_B1 = OFF_Y  + ROWS*64;  // 256
static constexpr int OFF_B2 = OFF_B1 + 256;      // 256
static constexpr int OFF_B3 = OFF_B2 + 256;      // 64
static constexpr int SMEM_FLOATS = OFF_B3 + 64;
static constexpr size_t SMEM_BYTES = (size_t)SMEM_FLOATS * sizeof(float);

__global__ __launch_bounds__(TH, 1)
void node_kernel(const float* __restrict__ y0, const float* __restrict__ tvec,
                 const float* __restrict__ W1, const float* __restrict__ b1,
                 const float* __restrict__ W2, const float* __restrict__ b2,
                 const float* __restrict__ W3, const float* __restrict__ b3,
                 float* __restrict__ out)
{
    extern __shared__ float smem[];
    float* sW1 = smem + OFF_W1;
    float* sW3 = smem + OFF_W3;
    float* sh1 = smem + OFF_H1;
    float* sh2 = smem + OFF_H2;
    float* sy  = smem + OFF_Y;
    float* sb1 = smem + OFF_B1;
    float* sb2 = smem + OFF_B2;
    float* sb3 = smem + OFF_B3;

    const int tid  = threadIdx.x;
    const int row0 = blockIdx.x * ROWS;

    // ---- Prologue: stage weights + y0, write t=0 output ----
    for (int i = tid; i < 64*256; i += TH) sW1[i] = W1[i];
    for (int i = tid; i < 256*64; i += TH) sW3[i] = W3[i];
    if (tid < 256) { sb1[tid] = b1[tid]; sb2[tid] = b2[tid]; }
    if (tid < 64)  { sb3[tid] = b3[tid]; }
    for (int i = tid; i < ROWS*64; i += TH) {
        float v = y0[(size_t)row0*64 + i];
        sy[i] = v;
        int r = i >> 6, d = i & 63;
        out[(size_t)(row0 + r) * Tt * 64 + d] = v;   // t = 0
    }
    const float dt = tvec[1] - tvec[0];
    __syncthreads();

    for (int step = 1; step < Tt; ++step) {
        // ---- GEMM1: h1 = relu(y @ W1 + b1)   [ROWS x 256] ----
        {
            const int j = tid;
            float acc[ROWS];
            #pragma unroll
            for (int r = 0; r < ROWS; r++) acc[r] = 0.f;

            #pragma unroll 1
            for (int k = 0; k < 64; k += 4) {
                const float w0 = sW1[(k+0)*256 + j];
                const float w1 = sW1[(k+1)*256 + j];
                const float w2 = sW1[(k+2)*256 + j];
                const float w3 = sW1[(k+3)*256 + j];
                #pragma unroll
                for (int r = 0; r < ROWS; r++) {
                    float4 yv = *(const float4*)&sy[r*64 + k];   // broadcast
                    acc[r] += yv.x*w0 + yv.y*w1 + yv.z*w2 + yv.w*w3;
                }
            }
            const float bb = sb1[j];
            #pragma unroll
            for (int r = 0; r < ROWS; r++)
                sh1[r*256 + j] = fmaxf(acc[r] + bb, 0.f);
        }
        __syncthreads();

        // ---- GEMM2: h2 = relu(h1 @ W2 + b2)   [ROWS x 256], W2 from L2 ----
        {
            const int j = tid;
            float acc[ROWS];
            #pragma unroll
            for (int r = 0; r < ROWS; r++) acc[r] = 0.f;

            // software-pipelined W2 column loads (prefetch next k-quad)
            float w[4], wn[4];
            #pragma unroll
            for (int i = 0; i < 4; i++) w[i] = W2[i*256 + j];

            #pragma unroll 1
            for (int k = 0; k < 256; k += 4) {
                const int kn = (k + 4) & 255;   // wrap keeps loads in-bounds
                #pragma unroll
                for (int i = 0; i < 4; i++) wn[i] = W2[(kn + i)*256 + j];

                #pragma unroll
                for (int r = 0; r < ROWS; r++) {
                    float4 hv = *(const float4*)&sh1[r*256 + k];  // broadcast
                    acc[r] += hv.x*w[0] + hv.y*w[1] + hv.z*w[2] + hv.w*w[3];
                }
                #pragma unroll
                for (int i = 0; i < 4; i++) w[i] = wn[i];
            }
            const float bb = sb2[j];
            #pragma unroll
            for (int r = 0; r < ROWS; r++)
                sh2[r*256 + j] = fmaxf(acc[r] + bb, 0.f);
        }
        __syncthreads();

        // ---- GEMM3 + Euler update: y += dt*(h2 @ W3 + b3), stream to out ----
        {
            const int d  = tid & 63;
            const int rg = tid >> 6;         // 0..3, 8 rows each
            float acc[8];
            #pragma unroll
            for (int r = 0; r < 8; r++) acc[r] = 0.f;

            #pragma unroll 1
            for (int k = 0; k < 256; k += 4) {
                const float w0 = sW3[(k+0)*64 + d];
                const float w1 = sW3[(k+1)*64 + d];
                const float w2 = sW3[(k+2)*64 + d];
                const float w3 = sW3[(k+3)*64 + d];
                #pragma unroll
                for (int r = 0; r < 8; r++) {
                    float4 hv = *(const float4*)&sh2[(rg*8 + r)*256 + k];
                    acc[r] += hv.x*w0 + hv.y*w1 + hv.z*w2 + hv.w*w3;
                }
            }
            const float bb = sb3[d];
            #pragma unroll
            for (int r = 0; r < 8; r++) {
                const int rr = rg*8 + r;
                float ynew = sy[rr*64 + d] + dt * (acc[r] + bb);
                sy[rr*64 + d] = ynew;
                out[(size_t)(row0 + rr) * Tt * 64 + (size_t)step * 64 + d] = ynew;
            }
        }
        __syncthreads();
    }
}

extern "C" void kernel_launch(void* const* d_in, const int* in_sizes, int n_in,
                              void* d_out, int out_size)
{
    const float* y0 = (const float*)d_in[0];
    const float* t  = (const float*)d_in[1];
    const float* W1 = (const float*)d_in[2];
    const float* b1 = (const float*)d_in[3];
    const float* W2 = (const float*)d_in[4];
    const float* b2 = (const float*)d_in[5];
    const float* W3 = (const float*)d_in[6];
    const float* b3 = (const float*)d_in[7];
    float* out = (float*)d_out;

    static bool attr_set = false;
    if (!attr_set) {
        cudaFuncSetAttribute(node_kernel,
                             cudaFuncAttributeMaxDynamicSharedMemorySize,
                             (int)SMEM_BYTES);
        attr_set = true;
    }

    node_kernel<<<Bsz / ROWS, TH, SMEM_BYTES>>>(y0, t, W1, b1, W2, b2, W3, b3, out);
}

// round 13
// speedup vs baseline: 1.0032x; 1.0015x over previous
#include <cuda_runtime.h>
#include <cuda_bf16.h>

// NeuralODE: y_{t+1} = y_t + dt * MLP(y_t), 199 steps, B=4096, D=64, H=256.
// Rows are independent -> single persistent-style kernel, each CTA owns 32 rows
// for all 200 steps. W1/W3/biases cached in SMEM; W2 (256KB) streamed from L2
// once per CTA per step with register accumulators acc[32] per thread.

#define ROWS 32
#define TH   256

static constexpr int Bsz = 4096;
static constexpr int Dd  = 64;
static constexpr int Hh  = 256;
static constexpr int Tt  = 200;

// SMEM layout (floats)
static constexpr int OFF_W1 = 0;                 // 64*256   = 16384
static constexpr int OFF_W3 = OFF_W1 + 64*256;   // 256*64   = 16384
static constexpr int OFF_H1 = OFF_W3 + 256*64;   // ROWS*256 = 8192
static constexpr int OFF_H2 = OFF_H1 + ROWS*256; // ROWS*256 = 8192
static constexpr int OFF_Y  = OFF_H2 + ROWS*256; // ROWS*64  = 2048
static constexpr int OFF_B1 = OFF_Y  + ROWS*64;  // 256
static constexpr int OFF_B2 = OFF_B1 + 256;      // 256
static constexpr int OFF_B3 = OFF_B2 + 256;      // 64
static constexpr int SMEM_FLOATS = OFF_B3 + 64;
static constexpr size_t SMEM_BYTES = (size_t)SMEM_FLOATS * sizeof(float);

__global__ __launch_bounds__(TH, 1)
void node_kernel(const float* __restrict__ y0, const float* __restrict__ tvec,
                 const float* __restrict__ W1, const float* __restrict__ b1,
                 const float* __restrict__ W2, const float* __restrict__ b2,
                 const float* __restrict__ W3, const float* __restrict__ b3,
                 float* __restrict__ out)
{
    extern __shared__ float smem[];
    float* sW1 = smem + OFF_W1;
    float* sW3 = smem + OFF_W3;
    float* sh1 = smem + OFF_H1;
    float* sh2 = smem + OFF_H2;
    float* sy  = smem + OFF_Y;
    float* sb1 = smem + OFF_B1;
    float* sb2 = smem + OFF_B2;
    float* sb3 = smem + OFF_B3;

    const int tid  = threadIdx.x;
    const int row0 = blockIdx.x * ROWS;

    // ---- Prologue: stage weights + y0, write t=0 output ----
    for (int i = tid; i < 64*256; i += TH) sW1[i] = W1[i];
    for (int i = tid; i < 256*64; i += TH) sW3[i] = W3[i];
    if (tid < 256) { sb1[tid] = b1[tid]; sb2[tid] = b2[tid]; }
    if (tid < 64)  { sb3[tid] = b3[tid]; }
    for (int i = tid; i < ROWS*64; i += TH) {
        float v = y0[(size_t)row0*64 + i];
        sy[i] = v;
        int r = i >> 6, d = i & 63;
        out[(size_t)(row0 + r) * Tt * 64 + d] = v;   // t = 0
    }
    const float dt = tvec[1] - tvec[0];
    __syncthreads();

    for (int step = 1; step < Tt; ++step) {
        // ---- GEMM1: h1 = relu(y @ W1 + b1)   [ROWS x 256] ----
        {
            const int j = tid;
            float acc[ROWS];
            #pragma unroll
            for (int r = 0; r < ROWS; r++) acc[r] = 0.f;

            #pragma unroll 1
            for (int k = 0; k < 64; k += 4) {
                const float w0 = sW1[(k+0)*256 + j];
                const float w1 = sW1[(k+1)*256 + j];
                const float w2 = sW1[(k+2)*256 + j];
                const float w3 = sW1[(k+3)*256 + j];
                #pragma unroll
                for (int r = 0; r < ROWS; r++) {
                    float4 yv = *(const float4*)&sy[r*64 + k];   // broadcast
                    acc[r] += yv.x*w0 + yv.y*w1 + yv.z*w2 + yv.w*w3;
                }
            }
            const float bb = sb1[j];
            #pragma unroll
            for (int r = 0; r < ROWS; r++)
                sh1[r*256 + j] = fmaxf(acc[r] + bb, 0.f);
        }
        __syncthreads();

        // ---- GEMM2: h2 = relu(h1 @ W2 + b2)   [ROWS x 256], W2 from L2 ----
        {
            const int j = tid;
            float acc[ROWS];
            #pragma unroll
            for (int r = 0; r < ROWS; r++) acc[r] = 0.f;

            // software-pipelined W2 column loads (prefetch next k-quad)
            float w[4], wn[4];
            #pragma unroll
            for (int i = 0; i < 4; i++) w[i] = W2[i*256 + j];

            #pragma unroll 1
            for (int k = 0; k < 256; k += 4) {
                const int kn = (k + 4) & 255;   // wrap keeps loads in-bounds
                #pragma unroll
                for (int i = 0; i < 4; i++) wn[i] = W2[(kn + i)*256 + j];

                #pragma unroll
                for (int r = 0; r < ROWS; r++) {
                    float4 hv = *(const float4*)&sh1[r*256 + k];  // broadcast
                    acc[r] += hv.x*w[0] + hv.y*w[1] + hv.z*w[2] + hv.w*w[3];
                }
                #pragma unroll
                for (int i = 0; i < 4; i++) w[i] = wn[i];
            }
            const float bb = sb2[j];
            #pragma unroll
            for (int r = 0; r < ROWS; r++)
                sh2[r*256 + j] = fmaxf(acc[r] + bb, 0.f);
        }
        __syncthreads();

        // ---- GEMM3 + Euler update: y += dt*(h2 @ W3 + b3), stream to out ----
        {
            const int d  = tid & 63;
            const int rg = tid >> 6;         // 0..3, 8 rows each
            float acc[8];
            #pragma unroll
            for (int r = 0; r < 8; r++) acc[r] = 0.f;

            #pragma unroll 1
            for (int k = 0; k < 256; k += 4) {
                const float w0 = sW3[(k+0)*64 + d];
                const float w1 = sW3[(k+1)*64 + d];
                const float w2 = sW3[(k+2)*64 + d];
                const float w3 = sW3[(k+3)*64 + d];
                #pragma unroll
                for (int r = 0; r < 8; r++) {
                    float4 hv = *(const float4*)&sh2[(rg*8 + r)*256 + k];
                    acc[r] += hv.x*w0 + hv.y*w1 + hv.z*w2 + hv.w*w3;
                }
            }
            const float bb = sb3[d];
            #pragma unroll
            for (int r = 0; r < 8; r++) {
                const int rr = rg*8 + r;
                float ynew = sy[rr*64 + d] + dt * (acc[r] + bb);
                sy[rr*64 + d] = ynew;
                out[(size_t)(row0 + rr) * Tt * 64 + (size_t)step * 64 + d] = ynew;
            }
        }
        __syncthreads();
    }
}

extern "C" void kernel_launch(void* const* d_in, const int* in_sizes, int n_in,
                              void* d_out, int out_size)
{
    const float* y0 = (const float*)d_in[0];
    const float* t  = (const float*)d_in[1];
    const float* W1 = (const float*)d_in[2];
    const float* b1 = (const float*)d_in[3];
    const float* W2 = (const float*)d_in[4];
    const float* b2 = (const float*)d_in[5];
    const float* W3 = (const float*)d_in[6];
    const float* b3 = (const float*)d_in[7];
    float* out = (float*)d_out;

    static bool attr_set = false;
    if (!attr_set) {
        cudaFuncSetAttribute(node_kernel,
                             cudaFuncAttributeMaxDynamicSharedMemorySize,
                             (int)SMEM_BYTES);
        attr_set = true;
    }

    node_kernel<<<Bsz / ROWS, TH, SMEM_BYTES>>>(y0, t, W1, b1, W2, b2, W3, b3, out);
}